// round 7
// baseline (speedup 1.0000x reference)
#include <cuda_runtime.h>
#include <cuda_bf16.h>

// Problem shape (fixed by setup_inputs): B=8, H=96, W=256
// corr_i: (N, 1, 1, W>>i) fp32, flow: (B, 2, H, W) fp32
// out: (B, 4*K, H, W) fp32 with K = 9 taps (R = 4)

namespace {

constexpr int Bsz = 8;
constexpr int Hsz = 96;
constexpr int Wsz = 256;
constexpr int HW  = Hsz * Wsz;          // 24576
constexpr int N   = Bsz * HW;           // 196608
constexpr int R   = 4;
constexpr int K   = 2 * R + 1;          // 9
constexpr int C   = 4 * K;              // 36 output channels

// Process TWO pyramid levels: batch both 10-float window loads up front
// (20 outstanding loads -> latency hiding), then interpolate + store both.
// All 9 taps of a level share w = d - floor(d) and window V[base..base+9],
// base = floor(d) - R; out_k = (1-w)*V[k] + w*V[k+1].
__device__ __forceinline__ void process_pair(
    const float* __restrict__ rowA, int WiA, float dA,
    const float* __restrict__ rowB, int WiB, float dB,
    float* __restrict__ outp)            // channel-strided by HW; 2*K channels
{
    float fdA = floorf(dA), fdB = floorf(dB);
    float wA = dA - fdA,    wB = dB - fdB;
    int baseA = (int)fdA - R;
    int baseB = (int)fdB - R;

    float va[K + 1], vb[K + 1];
#pragma unroll
    for (int j = 0; j <= K; ++j) {
        int ia = baseA + j;
        va[j] = (ia >= 0 && ia < WiA) ? __ldcs(rowA + ia) : 0.0f;
    }
#pragma unroll
    for (int j = 0; j <= K; ++j) {
        int ib = baseB + j;
        vb[j] = (ib >= 0 && ib < WiB) ? __ldcs(rowB + ib) : 0.0f;
    }

    float omwA = 1.0f - wA, omwB = 1.0f - wB;
#pragma unroll
    for (int k = 0; k < K; ++k)
        __stcs(outp + k * HW, omwA * va[k] + wA * va[k + 1]);
#pragma unroll
    for (int k = 0; k < K; ++k)
        __stcs(outp + (K + k) * HW, omwB * vb[k] + wB * vb[k + 1]);
}

__global__ void __launch_bounds__(128, 11)
corr_lookup_kernel(const float* __restrict__ c0,
                   const float* __restrict__ c1,
                   const float* __restrict__ c2,
                   const float* __restrict__ c3,
                   const float* __restrict__ flow,
                   float* __restrict__ out)
{
    int n = blockIdx.x * blockDim.x + threadIdx.x;
    if (n >= N) return;

    int b = n / HW;
    int r = n - b * HW;                  // h*W + w within the image

    // flow channel 0 (disparity) for this pixel
    float disp = __ldg(flow + (size_t)b * 2 * HW + r);

    float* outp = out + (size_t)b * C * HW + r;

    process_pair(c0 + (size_t)n * 256, 256, disp,
                 c1 + (size_t)n * 128, 128, disp * 0.5f,
                 outp);
    process_pair(c2 + (size_t)n * 64,  64,  disp * 0.25f,
                 c3 + (size_t)n * 32,  32,  disp * 0.125f,
                 outp + 2 * K * HW);
}

} // namespace

extern "C" void kernel_launch(void* const* d_in, const int* in_sizes, int n_in,
                              void* d_out, int out_size)
{
    const float* c0   = (const float*)d_in[0];
    const float* c1   = (const float*)d_in[1];
    const float* c2   = (const float*)d_in[2];
    const float* c3   = (const float*)d_in[3];
    const float* flow = (const float*)d_in[4];
    float* out = (float*)d_out;

    constexpr int TPB = 128;
    int blocks = (N + TPB - 1) / TPB;   // 1536
    corr_lookup_kernel<<<blocks, TPB>>>(c0, c1, c2, c3, flow, out);
}